// round 16
// baseline (speedup 1.0000x reference)
#include <cuda_runtime.h>
#include <cuda_fp16.h>
#include <math.h>
#include <stdint.h>

static constexpr int T_   = 2048;
static constexpr int B_   = 2;
static constexpr int E_   = 1024;
static constexpr int H_   = 16;
static constexpr int HD_  = 64;
static constexpr int MTOK = T_ * B_;   // 4096
static constexpr int BH_  = B_ * H_;   // 32
static constexpr int N3E  = 3 * E_;    // 3072

// Scratch (static device globals: allocation-free at launch time)
__device__ __half g_Xh[(size_t)MTOK * E_];
__device__ __half g_Wh[(size_t)N3E * E_];
__device__ __half g_OWh[(size_t)E_ * E_];
__device__ __half g_Q[(size_t)BH_ * T_ * HD_];
__device__ __half g_K[(size_t)BH_ * T_ * HD_];
__device__ __half g_Vt[(size_t)BH_ * HD_ * T_];   // [b,h,d,t]
__device__ __half g_P[(size_t)BH_ * T_ * T_];
__device__ __half g_ATT[(size_t)MTOK * E_];
__device__ float  g_rsi[(size_t)BH_ * T_];

__device__ __forceinline__ uint32_t pack_h2(float a, float b) {
    __half2 h = __floats2half2_rn(a, b);
    return *(uint32_t*)&h;
}
__device__ __forceinline__ void mma_f16(float* d, const uint32_t* a, const uint32_t* b) {
    asm volatile(
        "mma.sync.aligned.m16n8k16.row.col.f32.f16.f16.f32 "
        "{%0,%1,%2,%3}, {%4,%5,%6,%7}, {%8,%9}, {%0,%1,%2,%3};"
        : "+f"(d[0]), "+f"(d[1]), "+f"(d[2]), "+f"(d[3])
        : "r"(a[0]), "r"(a[1]), "r"(a[2]), "r"(a[3]), "r"(b[0]), "r"(b[1]));
}
__device__ __forceinline__ void cp16(uint32_t dst, const void* src) {
    asm volatile("cp.async.cg.shared.global [%0], [%1], 16;" :: "r"(dst), "l"(src));
}
__device__ __forceinline__ void ldm_x4(uint32_t* r, uint32_t a) {
    asm volatile("ldmatrix.sync.aligned.m8n8.x4.shared.b16 {%0,%1,%2,%3}, [%4];"
        : "=r"(r[0]), "=r"(r[1]), "=r"(r[2]), "=r"(r[3]) : "r"(a));
}

// ---------------------------------------------------------------------------
// FP16 HMMA GEMM. KC=64 chunks, S=2 cp.async ring (Round-14 proven).
// C = A(MxK) @ B^T, B is (N x K) row-major, fp32 accumulate.
// MODE 0: QKV epilogue; 1: out-proj.
// ---------------------------------------------------------------------------
template <int BM, int BN, int WM, int WN, int MODE>
__global__ void __launch_bounds__(256) gemm_h(
    const __half* __restrict__ A, const __half* __restrict__ Bm,
    const float* __restrict__ bias, void* __restrict__ Cv,
    int M, int N, int K)
{
    constexpr int KC   = 64;
    constexpr int SROW = 36;                 // b32 per smem row (64h + 4 pad)
    constexpr int S    = 2;
    constexpr int WARPS_N = BN / WN;
    constexpr int MT = WM / 16;
    constexpr int NT = WN / 8;
    constexpr int NP = NT / 2;
    constexpr int ACH = BM * 8 / 256;
    constexpr int BCH = BN * 8 / 256;
    constexpr int ASZ4 = BM * SROW * 4;
    constexpr int BSZ4 = BN * SROW * 4;

    extern __shared__ char sm[];
    const uint32_t sbA = (uint32_t)__cvta_generic_to_shared(sm);
    const uint32_t sbB = sbA + S * ASZ4;

    const int tid  = threadIdx.x;
    const int lane = tid & 31;
    const int warp = tid >> 5;
    const int wm   = warp / WARPS_N;
    const int wn   = warp % WARPS_N;
    const int i0   = blockIdx.y * BM;
    const int j0   = blockIdx.x * BN;
    const int lc   = lane & 3;
    const int lg   = lane >> 2;
    const int C    = K / KC;

    const int lrA = ((lane >> 3) & 1) * 8 + (lane & 7);
    const int lcA = (lane >> 4) * 4;
    const int lrB = ((lane >> 4) & 1) * 8 + (lane & 7);
    const int lcB = ((lane >> 3) & 1) * 4;

    float acc[MT][NT][4];
    #pragma unroll
    for (int i = 0; i < MT; i++)
        #pragma unroll
        for (int j = 0; j < NT; j++)
            #pragma unroll
            for (int q = 0; q < 4; q++) acc[i][j][q] = 0.f;

    auto issue = [&](int st, int c) {
        const int k0 = c * KC;
        #pragma unroll
        for (int v = 0; v < ACH; v++) {
            int f = tid + v * 256;
            int row = f >> 3, ch = f & 7;
            cp16(sbA + st * ASZ4 + (row * SROW + ch * 4) * 4,
                 A + (size_t)(i0 + row) * K + k0 + ch * 8);
        }
        #pragma unroll
        for (int v = 0; v < BCH; v++) {
            int f = tid + v * 256;
            int row = f >> 3, ch = f & 7;
            cp16(sbB + st * BSZ4 + (row * SROW + ch * 4) * 4,
                 Bm + (size_t)(j0 + row) * K + k0 + ch * 8);
        }
        asm volatile("cp.async.commit_group;");
    };

    issue(0, 0);
    for (int c = 0; c < C; c++) {
        const int st = c & 1;
        asm volatile("cp.async.wait_group 0;");
        __syncthreads();
        if (c + 1 < C) issue(st ^ 1, c + 1);

        #pragma unroll
        for (int s = 0; s < 4; s++) {
            const int kb = s * 8;
            uint32_t af[MT][4], bf[NP][4];
            #pragma unroll
            for (int i = 0; i < MT; i++) {
                int row = wm * WM + i * 16 + lrA;
                ldm_x4(af[i], sbA + st * ASZ4 + (row * SROW + kb + lcA) * 4);
            }
            #pragma unroll
            for (int p = 0; p < NP; p++) {
                int row = wn * WN + p * 16 + lrB;
                ldm_x4(bf[p], sbB + st * BSZ4 + (row * SROW + kb + lcB) * 4);
            }
            #pragma unroll
            for (int i = 0; i < MT; i++)
                #pragma unroll
                for (int j = 0; j < NT; j++)
                    mma_f16(acc[i][j], af[i], &bf[j >> 1][(j & 1) * 2]);
        }
    }

    #pragma unroll
    for (int i = 0; i < MT; i++) {
        #pragma unroll
        for (int j = 0; j < NT; j++) {
            const int r_lo = i0 + wm * WM + i * 16 + lg;
            const int c    = j0 + wn * WN + j * 8 + lc * 2;
            #pragma unroll
            for (int qh = 0; qh < 2; qh++) {
                const int r = r_lo + qh * 8;
                float v0 = acc[i][j][qh * 2 + 0];
                float v1 = acc[i][j][qh * 2 + 1];
                if (MODE == 0) {
                    v0 += __ldg(&bias[c]);
                    v1 += __ldg(&bias[c + 1]);
                    const int t   = r >> 1;
                    const int b   = r & 1;
                    const int seg = c >> 10;
                    const int cc  = c & 1023;
                    const int h   = cc >> 6;
                    const int d   = cc & 63;
                    if (seg == 0) {
                        const size_t off = (((size_t)(b * H_ + h) * T_ + t) * HD_) + d;
                        *(uint32_t*)&g_Q[off] = pack_h2(v0 * 0.125f, v1 * 0.125f);
                    } else if (seg == 1) {
                        const size_t off = (((size_t)(b * H_ + h) * T_ + t) * HD_) + d;
                        *(uint32_t*)&g_K[off] = pack_h2(v0, v1);
                    } else {
                        const size_t base = ((size_t)(b * H_ + h) * HD_ + d) * T_ + t;
                        g_Vt[base]      = __float2half_rn(v0);
                        g_Vt[base + T_] = __float2half_rn(v1);
                    }
                } else { // MODE 1
                    float* Co = (float*)Cv;
                    float2 w = make_float2(v0 + __ldg(&bias[c]), v1 + __ldg(&bias[c + 1]));
                    *(float2*)&Co[(size_t)r * N + c] = w;
                }
            }
        }
    }
}

// ---------------------------------------------------------------------------
// Fused attention v4 (Round-15 proven): hoisted Q frags + staged coalesced
// P stores through the dead Q smem region.
// ---------------------------------------------------------------------------
__global__ void __launch_bounds__(256, 2) attn_fused()
{
    constexpr int QOFF = 0;
    constexpr int KOFF = 4608;
    constexpr int VOFF = KOFF + 2 * 4608;    // 13824

    extern __shared__ char sm[];
    uint32_t* stage = (uint32_t*)sm;         // reuses Q region after j==0
    const uint32_t sb = (uint32_t)__cvta_generic_to_shared(sm);

    const int z  = blockIdx.y;
    const int i0 = blockIdx.x * 128;
    const __half* Qg = g_Q  + (size_t)z * T_ * HD_;
    const __half* Kg = g_K  + (size_t)z * T_ * HD_;
    const __half* Vg = g_Vt + (size_t)z * HD_ * T_;
    __half*       Pg = g_P  + (size_t)z * T_ * T_;

    const int tid  = threadIdx.x;
    const int lane = tid & 31;
    const int w    = tid >> 5;
    const int lc   = lane & 3;
    const int lg   = lane >> 2;
    const int lrA = ((lane >> 3) & 1) * 8 + (lane & 7);
    const int lcA = (lane >> 4) * 4;
    const int lrB = ((lane >> 4) & 1) * 8 + (lane & 7);
    const int lcB = ((lane >> 3) & 1) * 4;

    auto issueKV = [&](int buf, int jj) {
        const int j0 = jj * 128;
        const uint32_t kb = sb + (KOFF + buf * 4608) * 4;
        const uint32_t vb = sb + (VOFF + buf * 4352) * 4;
        #pragma unroll
        for (int v = 0; v < 4; v++) {           // K: 128 rows x 64h
            int f = tid + v * 256;
            int row = f >> 3, ch = f & 7;
            cp16(kb + (row * 36 + ch * 4) * 4,
                 Kg + (size_t)(j0 + row) * HD_ + ch * 8);
        }
        #pragma unroll
        for (int v = 0; v < 4; v++) {           // V: 64 rows x 128h
            int f = tid + v * 256;
            int row = f >> 4, ch = f & 15;
            cp16(vb + (row * 68 + ch * 4) * 4,
                 Vg + (size_t)row * T_ + j0 + ch * 8);
        }
        asm volatile("cp.async.commit_group;");
    };

    #pragma unroll
    for (int v = 0; v < 4; v++) {               // Q: 128 rows x 64h
        int f = tid + v * 256;
        int row = f >> 3, ch = f & 7;
        cp16(sb + (QOFF + row * 36 + ch * 4) * 4,
             Qg + (size_t)(i0 + row) * HD_ + ch * 8);
    }
    issueKV(0, 0);
    issueKV(1, 1);

    float acco[8][4];
    #pragma unroll
    for (int n = 0; n < 8; n++)
        #pragma unroll
        for (int q = 0; q < 4; q++) acco[n][q] = 0.f;
    float rs0 = 0.f, rs1 = 0.f;
    const int r0l = w * 16 + lg;
    const int row0 = i0 + r0l;

    uint32_t qf[4][4];

    for (int j = 0; j < 16; j++) {
        if (j < 15) asm volatile("cp.async.wait_group 1;");
        else        asm volatile("cp.async.wait_group 0;");
        __syncthreads();
        const int buf = j & 1;
        const uint32_t kb = sb + (KOFF + buf * 4608) * 4;
        const uint32_t vb = sb + (VOFF + buf * 4352) * 4;

        if (j == 0) {
            #pragma unroll
            for (int s = 0; s < 4; s++)
                ldm_x4(qf[s], sb + (QOFF + (w * 16 + lrA) * 36 + s * 8 + lcA) * 4);
            __syncthreads();
        }

        #pragma unroll
        for (int half = 0; half < 2; half++) {
            float accs[8][4];
            #pragma unroll
            for (int n = 0; n < 8; n++)
                #pragma unroll
                for (int q = 0; q < 4; q++) accs[n][q] = 0.f;

            #pragma unroll
            for (int s = 0; s < 4; s++) {
                uint32_t bf[4][4];
                #pragma unroll
                for (int p = 0; p < 4; p++)
                    ldm_x4(bf[p], kb + ((half * 64 + 16 * p + lrB) * 36 + s * 8 + lcB) * 4);
                #pragma unroll
                for (int n = 0; n < 8; n++)
                    mma_f16(accs[n], qf[s], &bf[n >> 1][(n & 1) * 2]);
            }

            uint32_t pf[4][4];
            #pragma unroll
            for (int n = 0; n < 8; n++) {
                float e0 = __expf(accs[n][0]), e1 = __expf(accs[n][1]);
                float e2 = __expf(accs[n][2]), e3 = __expf(accs[n][3]);
                rs0 += e0 + e1;
                rs1 += e2 + e3;
                uint32_t u01 = pack_h2(e0, e1);
                uint32_t u23 = pack_h2(e2, e3);
                stage[(r0l)     * 36 + 4 * n + lc] = u01;
                stage[(r0l + 8) * 36 + 4 * n + lc] = u23;
                pf[n >> 1][(n & 1) * 2]     = u01;
                pf[n >> 1][(n & 1) * 2 + 1] = u23;
            }

            #pragma unroll
            for (int s2 = 0; s2 < 4; s2++) {
                uint32_t bv[4][4];
                #pragma unroll
                for (int p = 0; p < 4; p++)
                    ldm_x4(bv[p], vb + ((16 * p + lrB) * 68 + (half * 4 + s2) * 8 + lcB) * 4);
                #pragma unroll
                for (int n = 0; n < 8; n++)
                    mma_f16(acco[n], pf[s2], &bv[n >> 1][(n & 1) * 2]);
            }

            __syncthreads();
            #pragma unroll
            for (int it = 0; it < 4; it++) {
                const int row = (tid >> 3) + it * 32;
                const int m   = tid & 7;
                uint4 val = *(uint4*)&stage[row * 36 + m * 4];
                *(uint4*)&Pg[(size_t)(i0 + row) * T_ + j * 128 + half * 64 + m * 8] = val;
            }
            __syncthreads();
        }

        if (j + 2 < 16) issueKV(buf, j + 2);
    }

    rs0 += __shfl_xor_sync(0xffffffffu, rs0, 1);
    rs0 += __shfl_xor_sync(0xffffffffu, rs0, 2);
    rs1 += __shfl_xor_sync(0xffffffffu, rs1, 1);
    rs1 += __shfl_xor_sync(0xffffffffu, rs1, 2);
    const float inv0 = 1.0f / rs0;
    const float inv1 = 1.0f / rs1;
    const int row1 = row0 + 8;
    if (lc == 0) {
        g_rsi[(size_t)z * T_ + row0] = inv0;
        g_rsi[(size_t)z * T_ + row1] = inv1;
    }
    const int b = z >> 4, h = z & 15;
    #pragma unroll
    for (int n = 0; n < 8; n++) {
        const int col = n * 8 + lc * 2;
        *(uint32_t*)&g_ATT[((size_t)row0 * B_ + b) * E_ + h * HD_ + col] =
            pack_h2(acco[n][0] * inv0, acco[n][1] * inv0);
        *(uint32_t*)&g_ATT[((size_t)row1 * B_ + b) * E_ + h * HD_ + col] =
            pack_h2(acco[n][2] * inv1, acco[n][3] * inv1);
    }
}

// ---------------------------------------------------------------------------
// Merged fp32->fp16 converts (x, in_proj_w, out_w in one launch).
// ---------------------------------------------------------------------------
__global__ void __launch_bounds__(256) convert_all(
    const float* __restrict__ x, const float* __restrict__ w,
    const float* __restrict__ ow)
{
    constexpr int NX = MTOK * E_;       // 4194304
    constexpr int NW = N3E * E_;        // 3145728
    constexpr int NO = E_ * E_;         // 1048576
    int i = (blockIdx.x * 256 + threadIdx.x) * 8;
    const float* s;
    __half* d;
    if (i < NX)                { s = x  + i;            d = g_Xh  + i; }
    else if (i < NX + NW)      { s = w  + (i - NX);     d = g_Wh  + (i - NX); }
    else if (i < NX + NW + NO) { s = ow + (i - NX - NW); d = g_OWh + (i - NX - NW); }
    else return;
    float4 a = *(const float4*)s;
    float4 b = *(const float4*)(s + 4);
    uint4 u;
    u.x = pack_h2(a.x, a.y); u.y = pack_h2(a.z, a.w);
    u.z = pack_h2(b.x, b.y); u.w = pack_h2(b.z, b.w);
    *(uint4*)d = u;
}

// ---------------------------------------------------------------------------
// head_sum, grid-stride with a SMALL grid (256 CTAs) so it can co-reside
// with the tensor-bound out-proj kernel instead of monopolizing the SMs.
// ---------------------------------------------------------------------------
__global__ void __launch_bounds__(256) head_sum(const __half* __restrict__ P,
                                                float* __restrict__ W)
{
    const size_t per_b  = (size_t)T_ * T_ / 8;
    const size_t total  = (size_t)B_ * per_b;
    const size_t stride = (size_t)gridDim.x * 256;
    for (size_t idx = (size_t)blockIdx.x * 256 + threadIdx.x; idx < total;
         idx += stride) {
        const size_t b   = idx / per_b;
        const size_t rem = idx % per_b;
        const int    tq  = (int)(rem / (T_ / 8));
        const uint4* base = (const uint4*)P + b * H_ * per_b + rem;
        float acc[8] = {0.f, 0.f, 0.f, 0.f, 0.f, 0.f, 0.f, 0.f};
        #pragma unroll
        for (int h = 0; h < H_; h++) {
            uint4 x = base[(size_t)h * per_b];
            const float inv = g_rsi[((size_t)b * H_ + h) * T_ + tq];
            const __half2* hp = (const __half2*)&x;
            #pragma unroll
            for (int k = 0; k < 4; k++) {
                float2 f = __half22float2(hp[k]);
                acc[2 * k]     += f.x * inv;
                acc[2 * k + 1] += f.y * inv;
            }
        }
        const float sc = 1.0f / (float)H_;
        float4 o0 = make_float4(acc[0] * sc, acc[1] * sc, acc[2] * sc, acc[3] * sc);
        float4 o1 = make_float4(acc[4] * sc, acc[5] * sc, acc[6] * sc, acc[7] * sc);
        ((float4*)W)[idx * 2]     = o0;
        ((float4*)W)[idx * 2 + 1] = o1;
    }
}

// ---------------------------------------------------------------------------
extern "C" void kernel_launch(void* const* d_in, const int* in_sizes, int n_in,
                              void* d_out, int out_size)
{
    const float* x     = (const float*)d_in[0];
    const float* in_w  = (const float*)d_in[1];
    const float* in_b  = (const float*)d_in[2];
    const float* out_w = (const float*)d_in[3];
    const float* out_b = (const float*)d_in[4];

    float* attn_out = (float*)d_out;                        // [T,B,E]
    float* w_out    = (float*)d_out + (size_t)MTOK * E_;    // [B,T,T]

    __half *Xh, *Wh, *P, *ATT, *OWh;
    cudaGetSymbolAddress((void**)&Xh,  g_Xh);
    cudaGetSymbolAddress((void**)&Wh,  g_Wh);
    cudaGetSymbolAddress((void**)&OWh, g_OWh);
    cudaGetSymbolAddress((void**)&P,   g_P);
    cudaGetSymbolAddress((void**)&ATT, g_ATT);

    constexpr int SM_GEMM  = 2 * (128 * 36 + 128 * 36) * 4;           // 73728
    constexpr int SM_FUSED = (13824 + 2 * 4352) * 4;                  // 90112
    cudaFuncSetAttribute((const void*)gemm_h<128,128,64,32,0>,
                         cudaFuncAttributeMaxDynamicSharedMemorySize, SM_GEMM);
    cudaFuncSetAttribute((const void*)gemm_h<128,128,64,32,1>,
                         cudaFuncAttributeMaxDynamicSharedMemorySize, SM_GEMM);
    cudaFuncSetAttribute((const void*)attn_fused,
                         cudaFuncAttributeMaxDynamicSharedMemorySize, SM_FUSED);

    cudaStream_t s2;
    cudaStreamCreateWithFlags(&s2, cudaStreamNonBlocking);
    cudaEvent_t eFork, eJoin;
    cudaEventCreateWithFlags(&eFork, cudaEventDisableTiming);
    cudaEventCreateWithFlags(&eJoin, cudaEventDisableTiming);

    // 0) fp32 -> fp16 conversions (single launch)
    {
        constexpr int NTOT = MTOK * E_ + N3E * E_ + E_ * E_;  // 8388608
        convert_all<<<NTOT / 8 / 256, 256>>>(x, in_w, out_w);
    }

    // 1) QKV projection -> Q, K (head layout), Vt (transposed)
    gemm_h<128,128,64,32,0><<<dim3(N3E/128, MTOK/128), 256, SM_GEMM>>>(
        Xh, Wh, in_b, nullptr, MTOK, N3E, E_);
    // 2) fused: expS -> P + rsi + O(normalized) -> g_ATT
    attn_fused<<<dim3(T_/128, BH_), 256, SM_FUSED>>>();

    // Fork: small-grid head_sum on s2 co-resides with out-proj on origin.
    cudaEventRecord(eFork, 0);
    cudaStreamWaitEvent(s2, eFork, 0);

    // 3) head-averaged attention weights (grid-stride, 256 CTAs, stream s2)
    head_sum<<<256, 256, 0, s2>>>(P, w_out);
    // 4) out projection -> first output (origin stream, truly concurrent)
    gemm_h<128,128,64,32,1><<<dim3(E_/128, MTOK/128), 256, SM_GEMM>>>(
        ATT, OWh, out_b, attn_out, MTOK, E_, E_);

    cudaEventRecord(eJoin, s2);
    cudaStreamWaitEvent(0, eJoin, 0);
}

// round 17
// speedup vs baseline: 1.1255x; 1.1255x over previous
#include <cuda_runtime.h>
#include <cuda_fp16.h>
#include <math.h>
#include <stdint.h>

static constexpr int T_   = 2048;
static constexpr int B_   = 2;
static constexpr int E_   = 1024;
static constexpr int H_   = 16;
static constexpr int HD_  = 64;
static constexpr int MTOK = T_ * B_;   // 4096
static constexpr int BH_  = B_ * H_;   // 32
static constexpr int N3E  = 3 * E_;    // 3072

// Scratch (static device globals: allocation-free at launch time)
__device__ __half g_Xh[(size_t)MTOK * E_];
__device__ __half g_Wh[(size_t)N3E * E_];
__device__ __half g_OWh[(size_t)E_ * E_];
__device__ __half g_Q[(size_t)BH_ * T_ * HD_];
__device__ __half g_K[(size_t)BH_ * T_ * HD_];
__device__ __half g_Vt[(size_t)BH_ * HD_ * T_];   // [b,h,d,t]
__device__ __half g_P[(size_t)BH_ * T_ * T_];
__device__ __half g_ATT[(size_t)MTOK * E_];
__device__ float  g_rsi[(size_t)BH_ * T_];

__device__ __forceinline__ uint32_t pack_h2(float a, float b) {
    __half2 h = __floats2half2_rn(a, b);
    return *(uint32_t*)&h;
}
__device__ __forceinline__ void mma_f16(float* d, const uint32_t* a, const uint32_t* b) {
    asm volatile(
        "mma.sync.aligned.m16n8k16.row.col.f32.f16.f16.f32 "
        "{%0,%1,%2,%3}, {%4,%5,%6,%7}, {%8,%9}, {%0,%1,%2,%3};"
        : "+f"(d[0]), "+f"(d[1]), "+f"(d[2]), "+f"(d[3])
        : "r"(a[0]), "r"(a[1]), "r"(a[2]), "r"(a[3]), "r"(b[0]), "r"(b[1]));
}
__device__ __forceinline__ void cp16(uint32_t dst, const void* src) {
    asm volatile("cp.async.cg.shared.global [%0], [%1], 16;" :: "r"(dst), "l"(src));
}
__device__ __forceinline__ void ldm_x4(uint32_t* r, uint32_t a) {
    asm volatile("ldmatrix.sync.aligned.m8n8.x4.shared.b16 {%0,%1,%2,%3}, [%4];"
        : "=r"(r[0]), "=r"(r[1]), "=r"(r[2]), "=r"(r[3]) : "r"(a));
}

// ---------------------------------------------------------------------------
// FP16 HMMA GEMM. KC=64 chunks, S=2 cp.async ring (Round-14 proven).
// C = A(MxK) @ B^T, B is (N x K) row-major, fp32 accumulate.
// MODE 0: QKV epilogue; 1: out-proj.
// ---------------------------------------------------------------------------
template <int BM, int BN, int WM, int WN, int MODE>
__global__ void __launch_bounds__(256) gemm_h(
    const __half* __restrict__ A, const __half* __restrict__ Bm,
    const float* __restrict__ bias, void* __restrict__ Cv,
    int M, int N, int K)
{
    constexpr int KC   = 64;
    constexpr int SROW = 36;                 // b32 per smem row (64h + 4 pad)
    constexpr int S    = 2;
    constexpr int WARPS_N = BN / WN;
    constexpr int MT = WM / 16;
    constexpr int NT = WN / 8;
    constexpr int NP = NT / 2;
    constexpr int ACH = BM * 8 / 256;
    constexpr int BCH = BN * 8 / 256;
    constexpr int ASZ4 = BM * SROW * 4;
    constexpr int BSZ4 = BN * SROW * 4;

    extern __shared__ char sm[];
    const uint32_t sbA = (uint32_t)__cvta_generic_to_shared(sm);
    const uint32_t sbB = sbA + S * ASZ4;

    const int tid  = threadIdx.x;
    const int lane = tid & 31;
    const int warp = tid >> 5;
    const int wm   = warp / WARPS_N;
    const int wn   = warp % WARPS_N;
    const int i0   = blockIdx.y * BM;
    const int j0   = blockIdx.x * BN;
    const int lc   = lane & 3;
    const int lg   = lane >> 2;
    const int C    = K / KC;

    const int lrA = ((lane >> 3) & 1) * 8 + (lane & 7);
    const int lcA = (lane >> 4) * 4;
    const int lrB = ((lane >> 4) & 1) * 8 + (lane & 7);
    const int lcB = ((lane >> 3) & 1) * 4;

    float acc[MT][NT][4];
    #pragma unroll
    for (int i = 0; i < MT; i++)
        #pragma unroll
        for (int j = 0; j < NT; j++)
            #pragma unroll
            for (int q = 0; q < 4; q++) acc[i][j][q] = 0.f;

    auto issue = [&](int st, int c) {
        const int k0 = c * KC;
        #pragma unroll
        for (int v = 0; v < ACH; v++) {
            int f = tid + v * 256;
            int row = f >> 3, ch = f & 7;
            cp16(sbA + st * ASZ4 + (row * SROW + ch * 4) * 4,
                 A + (size_t)(i0 + row) * K + k0 + ch * 8);
        }
        #pragma unroll
        for (int v = 0; v < BCH; v++) {
            int f = tid + v * 256;
            int row = f >> 3, ch = f & 7;
            cp16(sbB + st * BSZ4 + (row * SROW + ch * 4) * 4,
                 Bm + (size_t)(j0 + row) * K + k0 + ch * 8);
        }
        asm volatile("cp.async.commit_group;");
    };

    issue(0, 0);
    for (int c = 0; c < C; c++) {
        const int st = c & 1;
        asm volatile("cp.async.wait_group 0;");
        __syncthreads();
        if (c + 1 < C) issue(st ^ 1, c + 1);

        #pragma unroll
        for (int s = 0; s < 4; s++) {
            const int kb = s * 8;
            uint32_t af[MT][4], bf[NP][4];
            #pragma unroll
            for (int i = 0; i < MT; i++) {
                int row = wm * WM + i * 16 + lrA;
                ldm_x4(af[i], sbA + st * ASZ4 + (row * SROW + kb + lcA) * 4);
            }
            #pragma unroll
            for (int p = 0; p < NP; p++) {
                int row = wn * WN + p * 16 + lrB;
                ldm_x4(bf[p], sbB + st * BSZ4 + (row * SROW + kb + lcB) * 4);
            }
            #pragma unroll
            for (int i = 0; i < MT; i++)
                #pragma unroll
                for (int j = 0; j < NT; j++)
                    mma_f16(acc[i][j], af[i], &bf[j >> 1][(j & 1) * 2]);
        }
    }

    #pragma unroll
    for (int i = 0; i < MT; i++) {
        #pragma unroll
        for (int j = 0; j < NT; j++) {
            const int r_lo = i0 + wm * WM + i * 16 + lg;
            const int c    = j0 + wn * WN + j * 8 + lc * 2;
            #pragma unroll
            for (int qh = 0; qh < 2; qh++) {
                const int r = r_lo + qh * 8;
                float v0 = acc[i][j][qh * 2 + 0];
                float v1 = acc[i][j][qh * 2 + 1];
                if (MODE == 0) {
                    v0 += __ldg(&bias[c]);
                    v1 += __ldg(&bias[c + 1]);
                    const int t   = r >> 1;
                    const int b   = r & 1;
                    const int seg = c >> 10;
                    const int cc  = c & 1023;
                    const int h   = cc >> 6;
                    const int d   = cc & 63;
                    if (seg == 0) {
                        const size_t off = (((size_t)(b * H_ + h) * T_ + t) * HD_) + d;
                        *(uint32_t*)&g_Q[off] = pack_h2(v0 * 0.125f, v1 * 0.125f);
                    } else if (seg == 1) {
                        const size_t off = (((size_t)(b * H_ + h) * T_ + t) * HD_) + d;
                        *(uint32_t*)&g_K[off] = pack_h2(v0, v1);
                    } else {
                        const size_t base = ((size_t)(b * H_ + h) * HD_ + d) * T_ + t;
                        g_Vt[base]      = __float2half_rn(v0);
                        g_Vt[base + T_] = __float2half_rn(v1);
                    }
                } else { // MODE 1
                    float* Co = (float*)Cv;
                    float2 w = make_float2(v0 + __ldg(&bias[c]), v1 + __ldg(&bias[c + 1]));
                    *(float2*)&Co[(size_t)r * N + c] = w;
                }
            }
        }
    }
}

// ---------------------------------------------------------------------------
// Fused attention v4 (Round-15 proven): hoisted Q frags + staged coalesced
// P stores through the dead Q smem region.
// ---------------------------------------------------------------------------
__global__ void __launch_bounds__(256, 2) attn_fused()
{
    constexpr int QOFF = 0;
    constexpr int KOFF = 4608;
    constexpr int VOFF = KOFF + 2 * 4608;    // 13824

    extern __shared__ char sm[];
    uint32_t* stage = (uint32_t*)sm;         // reuses Q region after j==0
    const uint32_t sb = (uint32_t)__cvta_generic_to_shared(sm);

    const int z  = blockIdx.y;
    const int i0 = blockIdx.x * 128;
    const __half* Qg = g_Q  + (size_t)z * T_ * HD_;
    const __half* Kg = g_K  + (size_t)z * T_ * HD_;
    const __half* Vg = g_Vt + (size_t)z * HD_ * T_;
    __half*       Pg = g_P  + (size_t)z * T_ * T_;

    const int tid  = threadIdx.x;
    const int lane = tid & 31;
    const int w    = tid >> 5;
    const int lc   = lane & 3;
    const int lg   = lane >> 2;
    const int lrA = ((lane >> 3) & 1) * 8 + (lane & 7);
    const int lcA = (lane >> 4) * 4;
    const int lrB = ((lane >> 4) & 1) * 8 + (lane & 7);
    const int lcB = ((lane >> 3) & 1) * 4;

    auto issueKV = [&](int buf, int jj) {
        const int j0 = jj * 128;
        const uint32_t kb = sb + (KOFF + buf * 4608) * 4;
        const uint32_t vb = sb + (VOFF + buf * 4352) * 4;
        #pragma unroll
        for (int v = 0; v < 4; v++) {           // K: 128 rows x 64h
            int f = tid + v * 256;
            int row = f >> 3, ch = f & 7;
            cp16(kb + (row * 36 + ch * 4) * 4,
                 Kg + (size_t)(j0 + row) * HD_ + ch * 8);
        }
        #pragma unroll
        for (int v = 0; v < 4; v++) {           // V: 64 rows x 128h
            int f = tid + v * 256;
            int row = f >> 4, ch = f & 15;
            cp16(vb + (row * 68 + ch * 4) * 4,
                 Vg + (size_t)row * T_ + j0 + ch * 8);
        }
        asm volatile("cp.async.commit_group;");
    };

    #pragma unroll
    for (int v = 0; v < 4; v++) {               // Q: 128 rows x 64h
        int f = tid + v * 256;
        int row = f >> 3, ch = f & 7;
        cp16(sb + (QOFF + row * 36 + ch * 4) * 4,
             Qg + (size_t)(i0 + row) * HD_ + ch * 8);
    }
    issueKV(0, 0);
    issueKV(1, 1);

    float acco[8][4];
    #pragma unroll
    for (int n = 0; n < 8; n++)
        #pragma unroll
        for (int q = 0; q < 4; q++) acco[n][q] = 0.f;
    float rs0 = 0.f, rs1 = 0.f;
    const int r0l = w * 16 + lg;
    const int row0 = i0 + r0l;

    uint32_t qf[4][4];

    for (int j = 0; j < 16; j++) {
        if (j < 15) asm volatile("cp.async.wait_group 1;");
        else        asm volatile("cp.async.wait_group 0;");
        __syncthreads();
        const int buf = j & 1;
        const uint32_t kb = sb + (KOFF + buf * 4608) * 4;
        const uint32_t vb = sb + (VOFF + buf * 4352) * 4;

        if (j == 0) {
            #pragma unroll
            for (int s = 0; s < 4; s++)
                ldm_x4(qf[s], sb + (QOFF + (w * 16 + lrA) * 36 + s * 8 + lcA) * 4);
            __syncthreads();
        }

        #pragma unroll
        for (int half = 0; half < 2; half++) {
            float accs[8][4];
            #pragma unroll
            for (int n = 0; n < 8; n++)
                #pragma unroll
                for (int q = 0; q < 4; q++) accs[n][q] = 0.f;

            #pragma unroll
            for (int s = 0; s < 4; s++) {
                uint32_t bf[4][4];
                #pragma unroll
                for (int p = 0; p < 4; p++)
                    ldm_x4(bf[p], kb + ((half * 64 + 16 * p + lrB) * 36 + s * 8 + lcB) * 4);
                #pragma unroll
                for (int n = 0; n < 8; n++)
                    mma_f16(accs[n], qf[s], &bf[n >> 1][(n & 1) * 2]);
            }

            uint32_t pf[4][4];
            #pragma unroll
            for (int n = 0; n < 8; n++) {
                float e0 = __expf(accs[n][0]), e1 = __expf(accs[n][1]);
                float e2 = __expf(accs[n][2]), e3 = __expf(accs[n][3]);
                rs0 += e0 + e1;
                rs1 += e2 + e3;
                uint32_t u01 = pack_h2(e0, e1);
                uint32_t u23 = pack_h2(e2, e3);
                stage[(r0l)     * 36 + 4 * n + lc] = u01;
                stage[(r0l + 8) * 36 + 4 * n + lc] = u23;
                pf[n >> 1][(n & 1) * 2]     = u01;
                pf[n >> 1][(n & 1) * 2 + 1] = u23;
            }

            #pragma unroll
            for (int s2 = 0; s2 < 4; s2++) {
                uint32_t bv[4][4];
                #pragma unroll
                for (int p = 0; p < 4; p++)
                    ldm_x4(bv[p], vb + ((16 * p + lrB) * 68 + (half * 4 + s2) * 8 + lcB) * 4);
                #pragma unroll
                for (int n = 0; n < 8; n++)
                    mma_f16(acco[n], pf[s2], &bv[n >> 1][(n & 1) * 2]);
            }

            __syncthreads();
            #pragma unroll
            for (int it = 0; it < 4; it++) {
                const int row = (tid >> 3) + it * 32;
                const int m   = tid & 7;
                uint4 val = *(uint4*)&stage[row * 36 + m * 4];
                *(uint4*)&Pg[(size_t)(i0 + row) * T_ + j * 128 + half * 64 + m * 8] = val;
            }
            __syncthreads();
        }

        if (j + 2 < 16) issueKV(buf, j + 2);
    }

    rs0 += __shfl_xor_sync(0xffffffffu, rs0, 1);
    rs0 += __shfl_xor_sync(0xffffffffu, rs0, 2);
    rs1 += __shfl_xor_sync(0xffffffffu, rs1, 1);
    rs1 += __shfl_xor_sync(0xffffffffu, rs1, 2);
    const float inv0 = 1.0f / rs0;
    const float inv1 = 1.0f / rs1;
    const int row1 = row0 + 8;
    if (lc == 0) {
        g_rsi[(size_t)z * T_ + row0] = inv0;
        g_rsi[(size_t)z * T_ + row1] = inv1;
    }
    const int b = z >> 4, h = z & 15;
    #pragma unroll
    for (int n = 0; n < 8; n++) {
        const int col = n * 8 + lc * 2;
        *(uint32_t*)&g_ATT[((size_t)row0 * B_ + b) * E_ + h * HD_ + col] =
            pack_h2(acco[n][0] * inv0, acco[n][1] * inv0);
        *(uint32_t*)&g_ATT[((size_t)row1 * B_ + b) * E_ + h * HD_ + col] =
            pack_h2(acco[n][2] * inv1, acco[n][3] * inv1);
    }
}

// ---------------------------------------------------------------------------
// Merged fp32->fp16 converts (x, in_proj_w, out_w in one launch).
// ---------------------------------------------------------------------------
__global__ void __launch_bounds__(256) convert_all(
    const float* __restrict__ x, const float* __restrict__ w,
    const float* __restrict__ ow)
{
    constexpr int NX = MTOK * E_;       // 4194304
    constexpr int NW = N3E * E_;        // 3145728
    constexpr int NO = E_ * E_;         // 1048576
    int i = (blockIdx.x * 256 + threadIdx.x) * 8;
    const float* s;
    __half* d;
    if (i < NX)                { s = x  + i;             d = g_Xh  + i; }
    else if (i < NX + NW)      { s = w  + (i - NX);      d = g_Wh  + (i - NX); }
    else if (i < NX + NW + NO) { s = ow + (i - NX - NW); d = g_OWh + (i - NX - NW); }
    else return;
    float4 a = *(const float4*)s;
    float4 b = *(const float4*)(s + 4);
    uint4 u;
    u.x = pack_h2(a.x, a.y); u.y = pack_h2(a.z, a.w);
    u.z = pack_h2(b.x, b.y); u.w = pack_h2(b.z, b.w);
    *(uint4*)d = u;
}

// ---------------------------------------------------------------------------
// head_sum: full grid (one CTA per 256 8-elem units) — R15-proven 87% DRAM.
// ---------------------------------------------------------------------------
__global__ void __launch_bounds__(256) head_sum(const __half* __restrict__ P,
                                                float* __restrict__ W)
{
    const size_t idx = (size_t)blockIdx.x * 256 + threadIdx.x;   // 8-elem units
    const size_t per_b = (size_t)T_ * T_ / 8;
    if (idx >= (size_t)B_ * per_b) return;
    const size_t b   = idx / per_b;
    const size_t rem = idx % per_b;
    const int    tq  = (int)(rem / (T_ / 8));
    const uint4* base = (const uint4*)P + b * H_ * per_b + rem;
    float acc[8] = {0.f, 0.f, 0.f, 0.f, 0.f, 0.f, 0.f, 0.f};
    #pragma unroll
    for (int h = 0; h < H_; h++) {
        uint4 x = base[(size_t)h * per_b];
        const float inv = g_rsi[((size_t)b * H_ + h) * T_ + tq];
        const __half2* hp = (const __half2*)&x;
        #pragma unroll
        for (int k = 0; k < 4; k++) {
            float2 f = __half22float2(hp[k]);
            acc[2 * k]     += f.x * inv;
            acc[2 * k + 1] += f.y * inv;
        }
    }
    const float sc = 1.0f / (float)H_;
    float4 o0 = make_float4(acc[0] * sc, acc[1] * sc, acc[2] * sc, acc[3] * sc);
    float4 o1 = make_float4(acc[4] * sc, acc[5] * sc, acc[6] * sc, acc[7] * sc);
    ((float4*)W)[idx * 2]     = o0;
    ((float4*)W)[idx * 2 + 1] = o1;
}

// ---------------------------------------------------------------------------
extern "C" void kernel_launch(void* const* d_in, const int* in_sizes, int n_in,
                              void* d_out, int out_size)
{
    const float* x     = (const float*)d_in[0];
    const float* in_w  = (const float*)d_in[1];
    const float* in_b  = (const float*)d_in[2];
    const float* out_w = (const float*)d_in[3];
    const float* out_b = (const float*)d_in[4];

    float* attn_out = (float*)d_out;                        // [T,B,E]
    float* w_out    = (float*)d_out + (size_t)MTOK * E_;    // [B,T,T]

    __half *Xh, *Wh, *OWh, *P, *ATT;
    cudaGetSymbolAddress((void**)&Xh,  g_Xh);
    cudaGetSymbolAddress((void**)&Wh,  g_Wh);
    cudaGetSymbolAddress((void**)&OWh, g_OWh);
    cudaGetSymbolAddress((void**)&P,   g_P);
    cudaGetSymbolAddress((void**)&ATT, g_ATT);

    constexpr int SM_GEMM  = 2 * (128 * 36 + 128 * 36) * 4;           // 73728
    constexpr int SM_FUSED = (13824 + 2 * 4352) * 4;                  // 90112
    cudaFuncSetAttribute((const void*)gemm_h<128,128,64,32,0>,
                         cudaFuncAttributeMaxDynamicSharedMemorySize, SM_GEMM);
    cudaFuncSetAttribute((const void*)gemm_h<128,128,64,32,1>,
                         cudaFuncAttributeMaxDynamicSharedMemorySize, SM_GEMM);
    cudaFuncSetAttribute((const void*)attn_fused,
                         cudaFuncAttributeMaxDynamicSharedMemorySize, SM_FUSED);

    cudaStream_t s2;
    cudaStreamCreateWithFlags(&s2, cudaStreamNonBlocking);
    cudaEvent_t eFork, eJoin;
    cudaEventCreateWithFlags(&eFork, cudaEventDisableTiming);
    cudaEventCreateWithFlags(&eJoin, cudaEventDisableTiming);

    // 0) fp32 -> fp16 conversions (single launch)
    {
        constexpr int NTOT = MTOK * E_ + N3E * E_ + E_ * E_;  // 8388608
        convert_all<<<NTOT / 8 / 256, 256>>>(x, in_w, out_w);
    }

    // 1) QKV projection -> Q, K (head layout), Vt (transposed)
    gemm_h<128,128,64,32,0><<<dim3(N3E/128, MTOK/128), 256, SM_GEMM>>>(
        Xh, Wh, in_b, nullptr, MTOK, N3E, E_);
    // 2) fused: expS -> P + rsi + O(normalized) -> g_ATT
    attn_fused<<<dim3(T_/128, BH_), 256, SM_FUSED>>>();

    // Fork: head_sum on s2, out-proj on the origin stream, then join.
    cudaEventRecord(eFork, 0);
    cudaStreamWaitEvent(s2, eFork, 0);

    // 3) head-averaged attention weights (full grid, stream s2)
    head_sum<<<(unsigned)(((size_t)B_ * T_ * T_ / 8 + 255) / 256), 256, 0, s2>>>(
        P, w_out);
    // 4) out projection -> first output (origin stream)
    gemm_h<128,128,64,32,1><<<dim3(E_/128, MTOK/128), 256, SM_GEMM>>>(
        ATT, OWh, out_b, attn_out, MTOK, E_, E_);

    cudaEventRecord(eJoin, s2);
    cudaStreamWaitEvent(0, eJoin, 0);
}